// round 15
// baseline (speedup 1.0000x reference)
#include <cuda_runtime.h>
#include <cuda_bf16.h>
#include <math.h>
#include <stdint.h>

// Problem constants (fixed shapes)
#define BB 2
#define TT 4
#define NN 8192
#define CC 128
#define MM 1024
#define KK 9
#define HH 8
#define DHH 64
#define QKVC 1536         // 3 * HH * DHH
#define OUT_ELEMS (BB*TT*MM*CC)   // 1048576
#define TAIL (BB*MM*2)            // 4096
#define QSTRIDE 1540
#define NROPE (BB*MM*KK*32)       // 589824
#define NROWS (BB*TT*NN)          // 65536 rows of P
#define NTILES 12                 // 1536/128
#define MTILES 512                // 65536/128
#define GEMM_CTAS 146             // blocks 2..147 of the fused kernel

// smem row stride for mma tiles: 136 bf16 = 272 bytes (conflict-free ldmatrix)
#define TSTRIDE 136
#define TILE_B  (128 * TSTRIDE * 2)   // 34816 bytes per 128x128 bf16 tile

// smem layout of fused kernel
#define SM_AHI 0
#define SM_ALO TILE_B
#define SM_B0  (2*TILE_B)             // B buf0: hi at +0, lo at +TILE_B
#define SM_B1  (4*TILE_B)             // B buf1
#define GEMM_SMEM (6*TILE_B)          // 208896 bytes

// ----------------------------------------------------------------------------
// Scratch (device globals; allocation-free)
// ----------------------------------------------------------------------------
__device__ int   g_pivot_idx[BB*MM];
__device__ int   g_nbr[BB*MM*KK];
__device__ float g_rel[BB*MM*KK*2];
__device__ float g_rsin[NROPE];
__device__ float g_rcos[NROPE];
__device__ float g_P[(size_t)NROWS * QKVC];                 // 402 MB scratch
__device__ float g_obar[BB*TT*MM * 512];                    // 16 MB
__device__ __align__(16) __nv_bfloat16 g_whi[NTILES*128*128];  // W1 bf16 hi, [ntile][n][k]
__device__ __align__(16) __nv_bfloat16 g_wlo[NTILES*128*128];  // W1 bf16 lo

// ----------------------------------------------------------------------------
// mma.sync / ldmatrix / cp.async / f32x2 helpers (valid on plain sm_100)
// ----------------------------------------------------------------------------
__device__ __forceinline__ uint32_t smem_u32(const void* p) {
    uint32_t a;
    asm("{ .reg .u64 t; cvta.to.shared.u64 t, %1; cvt.u32.u64 %0, t; }" : "=r"(a) : "l"(p));
    return a;
}
__device__ __forceinline__ void ldsm_x4(uint32_t* r, uint32_t addr) {
    asm volatile("ldmatrix.sync.aligned.m8n8.x4.shared.b16 {%0,%1,%2,%3}, [%4];"
                 : "=r"(r[0]), "=r"(r[1]), "=r"(r[2]), "=r"(r[3]) : "r"(addr));
}
__device__ __forceinline__ void mma16816(float* c, const uint32_t* a, const uint32_t* b) {
    asm volatile("mma.sync.aligned.m16n8k16.row.col.f32.bf16.bf16.f32 "
                 "{%0,%1,%2,%3}, {%4,%5,%6,%7}, {%8,%9}, {%0,%1,%2,%3};"
                 : "+f"(c[0]), "+f"(c[1]), "+f"(c[2]), "+f"(c[3])
                 : "r"(a[0]), "r"(a[1]), "r"(a[2]), "r"(a[3]), "r"(b[0]), "r"(b[1]));
}
__device__ __forceinline__ void cp16(uint32_t dst, const void* src) {
    asm volatile("cp.async.cg.shared.global [%0], [%1], 16;" :: "r"(dst), "l"(src));
}
#define CP_COMMIT() asm volatile("cp.async.commit_group;" ::: "memory")
#define CP_WAIT(n)  asm volatile("cp.async.wait_group %0;" :: "n"(n) : "memory")

// packed fp32 pair ops (Blackwell f32x2 pipe; IEEE rn identical to scalar)
__device__ __forceinline__ unsigned long long f2pack(float a, float b) {
    unsigned long long r;
    asm("mov.b64 %0, {%1, %2};" : "=l"(r) : "f"(a), "f"(b));
    return r;
}
__device__ __forceinline__ void f2unpack(unsigned long long v, float* a, float* b) {
    asm("mov.b64 {%0, %1}, %2;" : "=f"(*a), "=f"(*b) : "l"(v));
}
__device__ __forceinline__ unsigned long long addx2(unsigned long long a, unsigned long long b) {
    unsigned long long r;
    asm("add.rn.f32x2 %0, %1, %2;" : "=l"(r) : "l"(a), "l"(b));
    return r;
}
__device__ __forceinline__ unsigned long long mulx2(unsigned long long a, unsigned long long b) {
    unsigned long long r;
    asm("mul.rn.f32x2 %0, %1, %2;" : "=l"(r) : "l"(a), "l"(b));
    return r;
}
__device__ __forceinline__ unsigned long long u64max(unsigned long long a, unsigned long long b) {
    return (a > b) ? a : b;
}

// 4-bit x 4-bit Morton interleave -> 8-bit cell id
__device__ __forceinline__ int morton4(int cx, int cy) {
    cx = (cx | (cx << 2)) & 0x33;
    cx = (cx | (cx << 1)) & 0x55;
    cy = (cy | (cy << 2)) & 0x33;
    cy = (cy | (cy << 1)) & 0x55;
    return cx | (cy << 1);
}

// ----------------------------------------------------------------------------
// Diagnostic shim: empty kernels to shift the ncu capture window onto
// gemm_fps_kernel (the profiler has captured "my 4th launch" every round).
// ----------------------------------------------------------------------------
__global__ void dummy_kernel() {}

// ----------------------------------------------------------------------------
// FPS body (512 threads, one block per batch) -- exact pruned FPS (R13-proven).
// ----------------------------------------------------------------------------
__device__ void fps_body(const float* __restrict__ pos, int bb, char* dynsmem)
{
    const int tid = threadIdx.x;           // 512
    const int wid = tid >> 5, lane = tid & 31;
    const float2* pb = (const float2*)(pos + (size_t)bb * NN * 2);

    unsigned long long* s_key = (unsigned long long*)dynsmem;   // [2][16] u64
    int*   s_cnt  = (int*)(dynsmem + 256);                      // 256
    int*   s_strt = s_cnt + 256;                                // 256
    float* s_px   = (float*)(s_strt + 256);                     // 8192
    float* s_py   = s_px + NN;                                  // 8192
    int*   s_oi   = (int*)(s_py + NN);                          // 8192

    // ---- Phase 0: Morton bucket sort ----
    for (int i = tid; i < 256; i += 512) s_cnt[i] = 0;
    __syncthreads();
    for (int i = tid; i < NN; i += 512) {
        float2 v = pb[i];
        int cx = max(0, min(15, (int)(v.x * 16.0f)));
        int cy = max(0, min(15, (int)(v.y * 16.0f)));
        atomicAdd(&s_cnt[morton4(cx, cy)], 1);
    }
    __syncthreads();
    if (tid == 0) {
        int acc = 0;
        for (int c = 0; c < 256; c++) { s_strt[c] = acc; acc += s_cnt[c]; }
    }
    __syncthreads();
    for (int i = tid; i < NN; i += 512) {
        float2 v = pb[i];
        int cx = max(0, min(15, (int)(v.x * 16.0f)));
        int cy = max(0, min(15, (int)(v.y * 16.0f)));
        int p = atomicAdd(&s_strt[morton4(cx, cy)], 1);
        s_px[p] = v.x; s_py[p] = v.y; s_oi[p] = i;
    }
    __syncthreads();

    // ---- registers: warp owns sorted [wid*512, wid*512+512) ----
    const int wbase = wid * 512;
    unsigned long long nx[8], ny[8];
    int   oidx[16];
    float dist[16];
    float lminx = 1e30f, lmaxx = -1e30f, lminy = 1e30f, lmaxy = -1e30f;
#pragma unroll
    for (int jj = 0; jj < 8; jj++) {
        int p0 = wbase + lane + 64 * jj;
        int p1 = p0 + 32;
        float x0 = s_px[p0], y0 = s_py[p0];
        float x1 = s_px[p1], y1 = s_py[p1];
        oidx[2*jj]   = s_oi[p0];
        oidx[2*jj+1] = s_oi[p1];
        nx[jj] = f2pack(-x0, -x1);
        ny[jj] = f2pack(-y0, -y1);
        dist[2*jj] = INFINITY; dist[2*jj+1] = INFINITY;
        lminx = fminf(lminx, fminf(x0, x1)); lmaxx = fmaxf(lmaxx, fmaxf(x0, x1));
        lminy = fminf(lminy, fminf(y0, y1)); lmaxy = fmaxf(lmaxy, fmaxf(y0, y1));
    }
    const float bminx = __uint_as_float(__reduce_min_sync(0xffffffffu, __float_as_uint(lminx)));
    const float bmaxx = __uint_as_float(__reduce_max_sync(0xffffffffu, __float_as_uint(lmaxx)));
    const float bminy = __uint_as_float(__reduce_min_sync(0xffffffffu, __float_as_uint(lminy)));
    const float bmaxy = __uint_as_float(__reduce_max_sync(0xffffffffu, __float_as_uint(lmaxy)));

    float bx, by;
    { float2 p0 = pb[0]; bx = p0.x; by = p0.y; }
    if (tid == 0) g_pivot_idx[bb * MM] = 0;

    float m_w = INFINITY;
    unsigned long long cached_key = 0;

    for (int s = 1; s < MM; s++) {
        float ddx = fmaxf(fmaxf(bminx - bx, bx - bmaxx), 0.0f);
        float ddy = fmaxf(fmaxf(bminy - by, by - bmaxy), 0.0f);
        float dlow2 = ddx * ddx + ddy * ddy;

        unsigned long long key;
        if (dlow2 * 0.999f > m_w) {
            key = cached_key;              // provably no dist can change
        } else {
            const unsigned long long bx2 = f2pack(bx, bx);
            const unsigned long long by2 = f2pack(by, by);
            float m = -INFINITY;
#pragma unroll
            for (int j = 0; j < 8; j++) {
                unsigned long long dx = addx2(nx[j], bx2);   // bx - px
                unsigned long long dy = addx2(ny[j], by2);   // by - py
                unsigned long long d  = addx2(mulx2(dx, dx), mulx2(dy, dy));
                float d0, d1; f2unpack(d, &d0, &d1);
                dist[2*j]   = fminf(dist[2*j],   d0);
                dist[2*j+1] = fminf(dist[2*j+1], d1);
                m = fmaxf(m, fmaxf(dist[2*j], dist[2*j+1]));
            }
            unsigned wmax = __reduce_max_sync(0xffffffffu, __float_as_uint(m));
            unsigned cand = 0xffffffffu;
            if (__float_as_uint(m) == wmax) {
                const float mm = __uint_as_float(wmax);
#pragma unroll
                for (int j = 0; j < 16; j++)
                    if (dist[j] == mm) {
                        unsigned gi = (unsigned)oidx[j];
                        cand = (gi < cand) ? gi : cand;
                    }
            }
            unsigned wmin = __reduce_min_sync(0xffffffffu, cand);
            key = ((unsigned long long)wmax << 32) | (unsigned)(~wmin);
            cached_key = key;
            m_w = __uint_as_float(wmax);
        }
        if (lane == 0) s_key[(s & 1) * 16 + wid] = key;
        __syncthreads();
        const ulonglong2* sk2 = (const ulonglong2*)(s_key + (s & 1) * 16);
        unsigned long long t8[8];
#pragma unroll
        for (int w = 0; w < 8; w++) {
            ulonglong2 v2 = sk2[w];
            t8[w] = u64max(v2.x, v2.y);
        }
        unsigned long long best = u64max(u64max(u64max(t8[0], t8[1]), u64max(t8[2], t8[3])),
                                         u64max(u64max(t8[4], t8[5]), u64max(t8[6], t8[7])));
        int bi = (int)(~(unsigned)(best & 0xffffffffu));
        float2 bp = pb[bi];
        bx = bp.x; by = bp.y;
        if (tid == 0) g_pivot_idx[bb * MM + s] = bi;
    }
}

// ----------------------------------------------------------------------------
// Fused kernel: blocks 0,1 -> FPS; blocks 2..147 -> persistent GEMM
// ----------------------------------------------------------------------------
__global__ void __launch_bounds__(512, 1) gemm_fps_kernel(const float* __restrict__ x,
                                                          const float* __restrict__ pos)
{
    extern __shared__ char smem[];
    if (blockIdx.x < 2) { fps_body(pos, blockIdx.x, smem); return; }

    const uint32_t sb = smem_u32(smem);
    const int tid  = threadIdx.x;
    const int wid  = tid >> 5, lane = tid & 31;
    const int wm   = wid & 3;        // m-slice (32 rows)
    const int wn   = wid >> 2;       // n-slice (32 cols)

    const uint32_t a_off = (uint32_t)(((wm * 32 + (lane & 15)) * TSTRIDE + ((lane >> 4) << 3)) * 2);
    const uint32_t b_off = (uint32_t)(((wn * 32 + ((lane >> 4) << 3) + (lane & 7)) * TSTRIDE
                                      + (((lane >> 3) & 1) << 3)) * 2);

    for (int m = (int)blockIdx.x - 2; m < MTILES; m += GEMM_CTAS) {
        {
            const char* bh = (const char*)g_whi;
            const char* bl = (const char*)g_wlo;
            for (int i = tid; i < 2048; i += 512) {
                int row = i >> 4, ch = i & 15;
                uint32_t off = (uint32_t)((row * TSTRIDE + ch * 8) * 2);
                cp16(sb + SM_B0 + off, bh + i * 16);
                cp16(sb + SM_B0 + TILE_B + off, bl + i * 16);
            }
            CP_COMMIT();
        }

        {
            const float4* xa = (const float4*)(x + (size_t)m * 128 * 128);
            for (int i = tid; i < 4096; i += 512) {
                int row = i >> 5, c = (i & 31) * 4;
                float4 v = xa[i];
                __nv_bfloat16 h0 = __float2bfloat16(v.x);
                __nv_bfloat16 h1 = __float2bfloat16(v.y);
                __nv_bfloat16 h2 = __float2bfloat16(v.z);
                __nv_bfloat16 h3 = __float2bfloat16(v.w);
                __nv_bfloat16 l0 = __float2bfloat16(v.x - __bfloat162float(h0));
                __nv_bfloat16 l1 = __float2bfloat16(v.y - __bfloat162float(h1));
                __nv_bfloat16 l2 = __float2bfloat16(v.z - __bfloat162float(h2));
                __nv_bfloat16 l3 = __float2bfloat16(v.w - __bfloat162float(h3));
                __nv_bfloat162* dh = (__nv_bfloat162*)(smem + SM_AHI + (row * TSTRIDE + c) * 2);
                __nv_bfloat162* dl = (__nv_bfloat162*)(smem + SM_ALO + (row * TSTRIDE + c) * 2);
                __nv_bfloat162 hp0; hp0.x = h0; hp0.y = h1;
                __nv_bfloat162 hp1; hp1.x = h2; hp1.y = h3;
                __nv_bfloat162 lp0; lp0.x = l0; lp0.y = l1;
                __nv_bfloat162 lp1; lp1.x = l2; lp1.y = l3;
                dh[0] = hp0; dh[1] = hp1;
                dl[0] = lp0; dl[1] = lp1;
            }
        }

        for (int nt = 0; nt < NTILES; nt++) {
            const uint32_t bufc = sb + ((nt & 1) ? SM_B1 : SM_B0);

            if (nt + 1 < NTILES) {
                const char* bh = (const char*)(g_whi + (size_t)(nt + 1) * 16384);
                const char* bl = (const char*)(g_wlo + (size_t)(nt + 1) * 16384);
                uint32_t dst = sb + (((nt + 1) & 1) ? SM_B1 : SM_B0);
                for (int i = tid; i < 2048; i += 512) {
                    int row = i >> 4, ch = i & 15;
                    uint32_t off = (uint32_t)((row * TSTRIDE + ch * 8) * 2);
                    cp16(dst + off, bh + i * 16);
                    cp16(dst + TILE_B + off, bl + i * 16);
                }
                CP_COMMIT();
                CP_WAIT(1);
            } else {
                CP_WAIT(0);
            }
            __syncthreads();

            float acc[32];
#pragma unroll
            for (int i = 0; i < 32; i++) acc[i] = 0.f;

#pragma unroll
            for (int pass = 0; pass < 3; pass++) {
                const uint32_t sa  = sb + (pass == 2 ? SM_ALO : SM_AHI) + a_off;
                const uint32_t sbb = bufc + (pass == 1 ? TILE_B : 0) + b_off;
#pragma unroll
                for (int ks = 0; ks < 8; ks++) {
                    uint32_t a0[4], a1[4];
                    ldsm_x4(a0, sa + ks * 32);
                    ldsm_x4(a1, sa + 16 * TSTRIDE * 2 + ks * 32);
#pragma unroll
                    for (int j2 = 0; j2 < 2; j2++) {
                        uint32_t b[4];
                        ldsm_x4(b, sbb + j2 * 16 * TSTRIDE * 2 + ks * 32);
                        mma16816(acc + (0 * 4 + j2 * 2 + 0) * 4, a0, b);
                        mma16816(acc + (0 * 4 + j2 * 2 + 1) * 4, a0, b + 2);
                        mma16816(acc + (1 * 4 + j2 * 2 + 0) * 4, a1, b);
                        mma16816(acc + (1 * 4 + j2 * 2 + 1) * 4, a1, b + 2);
                    }
                }
            }
            __syncthreads();

            {
                const int rbase = m * 128 + wm * 32 + (lane >> 2);
                const int cbase = nt * 128 + wn * 32 + (lane & 3) * 2;
#pragma unroll
                for (int i = 0; i < 2; i++) {
#pragma unroll
                    for (int j = 0; j < 4; j++) {
                        const float* c = acc + (i * 4 + j) * 4;
                        int r0 = rbase + i * 16;
                        int cc = cbase + j * 8;
                        *(float2*)(g_P + (size_t)r0 * QKVC + cc)       = make_float2(c[0], c[1]);
                        *(float2*)(g_P + (size_t)(r0 + 8) * QKVC + cc) = make_float2(c[2], c[3]);
                    }
                }
            }
        }
        __syncthreads();
    }
}

// ----------------------------------------------------------------------------
// Kernel 2: KNN (warp per pivot) + writes pivot_pos to output tail
// ----------------------------------------------------------------------------
__global__ void __launch_bounds__(256) knn_kernel(const float* __restrict__ pos,
                                                  float* __restrict__ outp,
                                                  int write_tail)
{
    const int gw   = blockIdx.x * (blockDim.x >> 5) + (threadIdx.x >> 5);
    const int lane = threadIdx.x & 31;
    const int bb   = gw >> 10;
    const float2* pb = (const float2*)(pos + (size_t)bb * NN * 2);
    const unsigned full = 0xffffffffu;

    const int pidx = g_pivot_idx[gw];
    const float2 pv = pb[pidx];
    const float a = __fadd_rn(__fmul_rn(pv.x, pv.x), __fmul_rn(pv.y, pv.y));

    float d[9]; int id[9];
#pragma unroll
    for (int q = 0; q < 9; q++) { d[q] = INFINITY; id[q] = 0x7fffffff; }

    for (int p = lane; p < NN; p += 32) {
        float2 q2 = pb[p];
        float b2  = __fadd_rn(__fmul_rn(q2.x, q2.x), __fmul_rn(q2.y, q2.y));
        float dot = __fadd_rn(__fmul_rn(pv.x, q2.x), __fmul_rn(pv.y, q2.y));
        float d2  = __fsub_rn(__fadd_rn(a, b2), __fmul_rn(2.0f, dot));
        if (d2 < d[8] || (d2 == d[8] && p < id[8])) {
            d[8] = d2; id[8] = p;
#pragma unroll
            for (int q = 8; q > 0; q--) {
                bool sw = (d[q] < d[q-1]) || (d[q] == d[q-1] && id[q] < id[q-1]);
                if (sw) {
                    float tv = d[q]; d[q] = d[q-1]; d[q-1] = tv;
                    int   ti = id[q]; id[q] = id[q-1]; id[q-1] = ti;
                }
            }
        }
    }
#pragma unroll
    for (int r = 0; r < 9; r++) {
        float bv = d[0]; int bi = id[0]; int bl = lane;
#pragma unroll
        for (int off = 16; off > 0; off >>= 1) {
            float ov = __shfl_down_sync(full, bv, off);
            int   oi = __shfl_down_sync(full, bi, off);
            int   ol = __shfl_down_sync(full, bl, off);
            if (ov < bv || (ov == bv && oi < bi)) { bv = ov; bi = oi; bl = ol; }
        }
        bi = __shfl_sync(full, bi, 0);
        bl = __shfl_sync(full, bl, 0);
        if (lane == bl) {
#pragma unroll
            for (int q = 0; q < 8; q++) { d[q] = d[q+1]; id[q] = id[q+1]; }
            d[8] = INFINITY; id[8] = 0x7fffffff;
        }
        if (lane == 0) {
            g_nbr[gw * KK + r] = bi;
            float2 q2 = pb[bi];
            g_rel[(gw * KK + r) * 2 + 0] = __fsub_rn(q2.x, pv.x);
            g_rel[(gw * KK + r) * 2 + 1] = __fsub_rn(q2.y, pv.y);
        }
    }
    if (lane == 0 && write_tail) {
        outp[OUT_ELEMS + gw * 2 + 0] = pv.x;
        outp[OUT_ELEMS + gw * 2 + 1] = pv.y;
    }
}

// ----------------------------------------------------------------------------
// sin/cos with explicit Cody-Waite range reduction (safe under fast-math)
// ----------------------------------------------------------------------------
__device__ __forceinline__ void sincos_red(float f, float* sn, float* cs)
{
    const float INV2PI = 0.15915494309189535f;
    const float C1 = 6.28318548202514648f;
    const float C2 = -1.74845560e-7f;
    float kq = rintf(f * INV2PI);
    float r = fmaf(-kq, C1, f);
    r = fmaf(-kq, C2, r);
    *sn = sinf(r);
    *cs = cosf(r);
}

// Kernel 2.5: precompute RoPE sin/cos (t-invariant)
__global__ void __launch_bounds__(256) rope_kernel()
{
    int idx = blockIdx.x * 256 + threadIdx.x;
    if (idx >= NROPE) return;
    int i    = idx & 15;
    int half = (idx >> 4) & 1;
    int rest = idx >> 5;
    int s    = rest % 9;
    int g    = rest / 9;
    float rel = g_rel[(g * KK + s) * 2 + half];
    float invf = __powf(10000.0f, -(float)i * (1.0f / 16.0f));
    float f = rel * 2048.0f * invf;
    float sn, cs;
    sincos_red(f, &sn, &cs);
    g_rsin[idx] = sn;
    g_rcos[idx] = cs;
}

// ----------------------------------------------------------------------------
// Kernel 0: convert W1 (=W_qkv rows 0..127) into bf16 hi/lo, layout [ntile][n][k]
// ----------------------------------------------------------------------------
__global__ void __launch_bounds__(256) wprep_kernel(const float* __restrict__ Wq)
{
    int idx = blockIdx.x * 256 + threadIdx.x;
    if (idx >= NTILES * 16384) return;
    int ntile = idx >> 14;
    int e = idx & 16383;
    int n = e >> 7, k = e & 127;
    float w = Wq[(size_t)k * QKVC + ntile * 128 + n];
    __nv_bfloat16 hi = __float2bfloat16(w);
    __nv_bfloat16 lo = __float2bfloat16(w - __bfloat162float(hi));
    g_whi[idx] = hi;
    g_wlo[idx] = lo;
}

// ----------------------------------------------------------------------------
// Kernel 4: group kernel, warp-per-head (R14 form, unchanged).
// ----------------------------------------------------------------------------
__global__ void __launch_bounds__(256) group_kernel(const float* __restrict__ Wq)
{
    extern __shared__ float sm[];
    float* s_qkv  = sm;                        // 9 * QSTRIDE
    float* s_dots = s_qkv + 9 * QSTRIDE;       // 648
    float* s_w    = s_dots + 648;              // 72
    float* s_rel  = s_w + 72;                  // 18
    int*   s_nbr  = (int*)(s_rel + 18);        // 9 (+pad)

    const int g   = blockIdx.x;
    const int bb  = g >> 12;
    const int tt  = (g >> 10) & 3;
    const int mi  = g & 1023;
    const int tid = threadIdx.x;
    const int base = (bb << 10) + mi;          // b*M + m

    if (tid < 9)  s_nbr[tid] = g_nbr[base * KK + tid];
    if (tid < 18) s_rel[tid] = g_rel[base * KK * 2 + tid];
    __syncthreads();

    // gather: qkv[s] = P[nbr[s]] + rel_x * W2a + rel_y * W2b
    const float* Pbt = g_P + (size_t)((bb * TT + tt)) * NN * QKVC;
    const float* W2a = Wq + (size_t)128 * QKVC;
    const float* W2b = Wq + (size_t)129 * QKVC;
    for (int idx = tid; idx < 9 * 384; idx += 256) {
        int sl = idx / 384;
        int c4 = idx - sl * 384;
        float4 p  = *(const float4*)(Pbt + (size_t)s_nbr[sl] * QKVC + c4 * 4);
        float4 wa = *(const float4*)(W2a + c4 * 4);
        float4 wb = *(const float4*)(W2b + c4 * 4);
        float rx = s_rel[sl * 2], ry = s_rel[sl * 2 + 1];
        float4 r;
        r.x = p.x + rx * wa.x + ry * wb.x;
        r.y = p.y + rx * wa.y + ry * wb.y;
        r.z = p.z + rx * wa.z + ry * wb.z;
        r.w = p.w + rx * wa.w + ry * wb.w;
        *(float4*)(s_qkv + sl * QSTRIDE + c4 * 4) = r;
    }
    __syncthreads();   // the ONLY block barrier

    // ---- warp-per-head pipeline: warp h owns head h ----
    const int h = tid >> 5;            // head = warp id
    const int lane = tid & 31;

    // RoPE: lane -> (half, i); same index math as before
    {
        const int half = lane >> 4, i = lane & 15;
        const int bq = h * 64 + half * 32 + i;
#pragma unroll
        for (int s = 0; s < 9; s++) {
            int ridx = ((base * KK + s) * 2 + half) * 16 + i;
            float sn = g_rsin[ridx];
            float cs = g_rcos[ridx];
            float* row = s_qkv + s * QSTRIDE;
            float qa = row[bq], qb = row[bq + 16];
            row[bq]      = qa * cs - qb * sn;
            row[bq + 16] = qb * cs + qa * sn;
            float ka = row[512 + bq], kb = row[512 + bq + 16];
            row[512 + bq]      = ka * cs - kb * sn;
            row[512 + bq + 16] = kb * cs + ka * sn;
        }
    }
    __syncwarp();

    // dots[i][j] for this head (81 dots striped over lanes)
    for (int idx = lane; idx < 81; idx += 32) {
        int qi = idx / 9, kj = idx - qi * 9;
        const float* qp = s_qkv + qi * QSTRIDE + h * 64;
        const float* kp = s_qkv + kj * QSTRIDE + 512 + h * 64;
        float a2 = 0.f;
#pragma unroll
        for (int dd = 0; dd < 64; dd++) a2 = fmaf(qp[dd], kp[dd], a2);
        s_dots[h * 81 + idx] = a2 * 0.125f;
    }
    __syncwarp();

    // softmax per row (9 rows, lanes 0..8)
    if (lane < 9) {
        float* row = s_dots + h * 81 + lane * 9;
        float mx = row[0];
#pragma unroll
        for (int j = 1; j < 9; j++) mx = fmaxf(mx, row[j]);
        float sum = 0.f;
#pragma unroll
        for (int j = 0; j < 9; j++) { float e = expf(row[j] - mx); row[j] = e; sum += e; }
        float inv = 1.0f / sum;
#pragma unroll
        for (int j = 0; j < 9; j++) row[j] *= inv;
    }
    __syncwarp();

    // column sums: w[j] = sum_i attn[i][j] (lanes 0..8)
    if (lane < 9) {
        float s2 = 0.f;
#pragma unroll
        for (int i = 0; i < 9; i++) s2 += s_dots[h * 81 + i * 9 + lane];
        s_w[h * 9 + lane] = s2;
    }
    __syncwarp();

    // obar: 64 dims for this head, 2 per lane
    for (int dd = lane; dd < 64; dd += 32) {
        float a3 = 0.f;
#pragma unroll
        for (int j = 0; j < 9; j++)
            a3 = fmaf(s_w[h * 9 + j], s_qkv[j * QSTRIDE + 1024 + h * 64 + dd], a3);
        g_obar[(size_t)g * 512 + h * 64 + dd] = a3 * (1.0f / 9.0f);
    }
}

// ----------------------------------------------------------------------------
// Kernel 5: out = obar @ W_out + b_out   (8192 x 128 x 512)
// ----------------------------------------------------------------------------
#define OPROWS 64
__global__ void __launch_bounds__(256) outproj_kernel(const float* __restrict__ Wo,
                                                      const float* __restrict__ bo,
                                                      float* __restrict__ out)
{
    extern __shared__ float smo[];
    float* sA = smo;             // 64 x 128
    float* sB = sA + OPROWS*128; // 128 x 128

    const int row0 = blockIdx.x * OPROWS;
    const int tid = threadIdx.x;
    const int tr = tid >> 4, tc = tid & 15;

    float acc[4][8];
#pragma unroll
    for (int i = 0; i < 4; i++)
#pragma unroll
        for (int j = 0; j < 8; j++) acc[i][j] = 0.f;

    for (int kc = 0; kc < 4; kc++) {
        __syncthreads();
        for (int i = tid; i < OPROWS * 32; i += 256) {
            int r = i >> 5, c4 = (i & 31) * 4;
            *(float4*)(sA + r * 128 + c4) =
                *(const float4*)(g_obar + (size_t)(row0 + r) * 512 + kc * 128 + c4);
        }
        for (int i = tid; i < 128 * 32; i += 256) {
            int r = i >> 5, c4 = (i & 31) * 4;
            *(float4*)(sB + r * 128 + c4) =
                *(const float4*)(Wo + (size_t)(kc * 128 + r) * 128 + c4);
        }
        __syncthreads();
        for (int k = 0; k < 128; k++) {
            float b8[8];
#pragma unroll
            for (int j = 0; j < 8; j++) b8[j] = sB[k * 128 + tc + 16 * j];
#pragma unroll
            for (int i = 0; i < 4; i++) {
                float a = sA[(tr * 4 + i) * 128 + k];
#pragma unroll
                for (int j = 0; j < 8; j++) acc[i][j] = fmaf(a, b8[j], acc[i][j]);
            }
        }
    }
#pragma unroll
    for (int i = 0; i < 4; i++) {
        int row = row0 + tr * 4 + i;
#pragma unroll
        for (int j = 0; j < 8; j++) {
            int c = tc + 16 * j;
            out[(size_t)row * 128 + c] = acc[i][j] + bo[c];
        }
    }
}

// ----------------------------------------------------------------------------
// Launch (dummies shift the ncu capture window onto gemm_fps_kernel)
// ----------------------------------------------------------------------------
extern "C" void kernel_launch(void* const* d_in, const int* in_sizes, int n_in,
                              void* d_out, int out_size)
{
    const float* x   = (const float*)d_in[0];
    const float* pos = (const float*)d_in[1];
    const float* Wq  = (const float*)d_in[2];
    const float* Wo  = (const float*)d_in[3];
    const float* bo  = (const float*)d_in[4];
    float* out = (float*)d_out;

    int write_tail = (out_size >= OUT_ELEMS + TAIL) ? 1 : 0;

    const int group_smem = (9 * QSTRIDE + 648 + 72 + 18 + 16) * 4;
    const int op_smem = (OPROWS * 128 + 128 * 128) * 4;

    static int attr_set = 0;
    if (!attr_set) {
        cudaFuncSetAttribute(gemm_fps_kernel, cudaFuncAttributeMaxDynamicSharedMemorySize, GEMM_SMEM);
        cudaFuncSetAttribute(group_kernel, cudaFuncAttributeMaxDynamicSharedMemorySize, group_smem);
        cudaFuncSetAttribute(outproj_kernel, cudaFuncAttributeMaxDynamicSharedMemorySize, op_smem);
        attr_set = 1;
    }

    wprep_kernel<<<(NTILES * 16384 + 255) / 256, 256>>>(Wq);
    dummy_kernel<<<1, 32>>>();
    dummy_kernel<<<1, 32>>>();
    gemm_fps_kernel<<<2 + GEMM_CTAS, 512, GEMM_SMEM>>>(x, pos);
    knn_kernel<<<(BB * MM) / 8, 256>>>(pos, out, write_tail);
    rope_kernel<<<(NROPE + 255) / 256, 256>>>();
    group_kernel<<<BB * TT * MM, 256, group_smem>>>(Wq);
    outproj_kernel<<<BB * TT * MM / OPROWS, 256, op_smem>>>(Wo, bo, out);
}

// round 16
// speedup vs baseline: 1.2573x; 1.2573x over previous
#include <cuda_runtime.h>
#include <cuda_bf16.h>
#include <math.h>
#include <stdint.h>

// Problem constants (fixed shapes)
#define BB 2
#define TT 4
#define NN 8192
#define CC 128
#define MM 1024
#define KK 9
#define HH 8
#define DHH 64
#define QKVC 1536         // 3 * HH * DHH
#define OUT_ELEMS (BB*TT*MM*CC)   // 1048576
#define TAIL (BB*MM*2)            // 4096
#define QSTRIDE 1540
#define NROPE (BB*MM*KK*32)       // 589824
#define NROWS (BB*TT*NN)          // 65536 rows of P
#define NTILES 12                 // 1536/128
#define MTILES 512                // 65536/128
#define GEMM_CTAS 146             // blocks 2..147 of the fused kernel

// smem row stride for mma tiles: 136 bf16 = 272 bytes (conflict-free ldmatrix)
#define TSTRIDE 136
#define TILE_B  (128 * TSTRIDE * 2)   // 34816 bytes per 128x128 bf16 tile

// smem layout of fused kernel
#define SM_AHI 0
#define SM_ALO TILE_B
#define SM_B0  (2*TILE_B)             // B buf0: hi at +0, lo at +TILE_B
#define SM_B1  (4*TILE_B)             // B buf1
#define GEMM_SMEM (6*TILE_B)          // 208896 bytes

// ----------------------------------------------------------------------------
// Scratch (device globals; allocation-free)
// ----------------------------------------------------------------------------
__device__ int   g_pivot_idx[BB*MM];
__device__ int   g_nbr[BB*MM*KK];
__device__ float g_rel[BB*MM*KK*2];
__device__ float g_rsin[NROPE];
__device__ float g_rcos[NROPE];
__device__ float g_P[(size_t)NROWS * QKVC];                 // 402 MB scratch
__device__ float g_obar[BB*TT*MM * 512];                    // 16 MB
__device__ __align__(16) __nv_bfloat16 g_whi[NTILES*128*128];  // W1 bf16 hi, [ntile][n][k]
__device__ __align__(16) __nv_bfloat16 g_wlo[NTILES*128*128];  // W1 bf16 lo

// ----------------------------------------------------------------------------
// mma.sync / ldmatrix / cp.async / f32x2 helpers (valid on plain sm_100)
// ----------------------------------------------------------------------------
__device__ __forceinline__ uint32_t smem_u32(const void* p) {
    uint32_t a;
    asm("{ .reg .u64 t; cvta.to.shared.u64 t, %1; cvt.u32.u64 %0, t; }" : "=r"(a) : "l"(p));
    return a;
}
__device__ __forceinline__ void ldsm_x4(uint32_t* r, uint32_t addr) {
    asm volatile("ldmatrix.sync.aligned.m8n8.x4.shared.b16 {%0,%1,%2,%3}, [%4];"
                 : "=r"(r[0]), "=r"(r[1]), "=r"(r[2]), "=r"(r[3]) : "r"(addr));
}
__device__ __forceinline__ void mma16816(float* c, const uint32_t* a, const uint32_t* b) {
    asm volatile("mma.sync.aligned.m16n8k16.row.col.f32.bf16.bf16.f32 "
                 "{%0,%1,%2,%3}, {%4,%5,%6,%7}, {%8,%9}, {%0,%1,%2,%3};"
                 : "+f"(c[0]), "+f"(c[1]), "+f"(c[2]), "+f"(c[3])
                 : "r"(a[0]), "r"(a[1]), "r"(a[2]), "r"(a[3]), "r"(b[0]), "r"(b[1]));
}
__device__ __forceinline__ void cp16(uint32_t dst, const void* src) {
    asm volatile("cp.async.cg.shared.global [%0], [%1], 16;" :: "r"(dst), "l"(src));
}
#define CP_COMMIT() asm volatile("cp.async.commit_group;" ::: "memory")
#define CP_WAIT(n)  asm volatile("cp.async.wait_group %0;" :: "n"(n) : "memory")

// packed fp32 pair ops (Blackwell f32x2 pipe; IEEE rn identical to scalar)
__device__ __forceinline__ unsigned long long f2pack(float a, float b) {
    unsigned long long r;
    asm("mov.b64 %0, {%1, %2};" : "=l"(r) : "f"(a), "f"(b));
    return r;
}
__device__ __forceinline__ void f2unpack(unsigned long long v, float* a, float* b) {
    asm("mov.b64 {%0, %1}, %2;" : "=f"(*a), "=f"(*b) : "l"(v));
}
__device__ __forceinline__ unsigned long long addx2(unsigned long long a, unsigned long long b) {
    unsigned long long r;
    asm("add.rn.f32x2 %0, %1, %2;" : "=l"(r) : "l"(a), "l"(b));
    return r;
}
__device__ __forceinline__ unsigned long long mulx2(unsigned long long a, unsigned long long b) {
    unsigned long long r;
    asm("mul.rn.f32x2 %0, %1, %2;" : "=l"(r) : "l"(a), "l"(b));
    return r;
}
__device__ __forceinline__ unsigned long long u64max(unsigned long long a, unsigned long long b) {
    return (a > b) ? a : b;
}

// 4-bit x 4-bit Morton interleave -> 8-bit cell id
__device__ __forceinline__ int morton4(int cx, int cy) {
    cx = (cx | (cx << 2)) & 0x33;
    cx = (cx | (cx << 1)) & 0x55;
    cy = (cy | (cy << 2)) & 0x33;
    cy = (cy | (cy << 1)) & 0x55;
    return cx | (cy << 1);
}

// ----------------------------------------------------------------------------
// Diagnostic shim: keeps the ncu capture window on gemm_fps_kernel.
// ----------------------------------------------------------------------------
__global__ void dummy_kernel() {}

// ----------------------------------------------------------------------------
// FPS body (512 threads, one block per batch) -- exact pruned FPS.
// R16: full pos copy in smem (s_op) so the per-step pivot load is one LDS.64
// instead of a global load through gemm-saturated L2.
// ----------------------------------------------------------------------------
__device__ void fps_body(const float* __restrict__ pos, int bb, char* dynsmem)
{
    const int tid = threadIdx.x;           // 512
    const int wid = tid >> 5, lane = tid & 31;
    const float2* pb = (const float2*)(pos + (size_t)bb * NN * 2);

    unsigned long long* s_key = (unsigned long long*)dynsmem;   // [2][16] u64 (256 B)
    int*    s_cnt  = (int*)(dynsmem + 256);                     // 256 ints
    int*    s_strt = s_cnt + 256;                               // 256 ints
    float*  s_px   = (float*)(s_strt + 256);                    // 8192 f
    float*  s_py   = s_px + NN;                                 // 8192 f
    int*    s_oi   = (int*)(s_py + NN);                         // 8192 i
    float2* s_op   = (float2*)(s_oi + NN);                      // 8192 float2 (64 KB)

    // ---- Phase 0: Morton bucket sort + pos copy into smem ----
    for (int i = tid; i < 256; i += 512) s_cnt[i] = 0;
    __syncthreads();
    for (int i = tid; i < NN; i += 512) {
        float2 v = pb[i];
        s_op[i] = v;
        int cx = max(0, min(15, (int)(v.x * 16.0f)));
        int cy = max(0, min(15, (int)(v.y * 16.0f)));
        atomicAdd(&s_cnt[morton4(cx, cy)], 1);
    }
    __syncthreads();
    if (tid == 0) {
        int acc = 0;
        for (int c = 0; c < 256; c++) { s_strt[c] = acc; acc += s_cnt[c]; }
    }
    __syncthreads();
    for (int i = tid; i < NN; i += 512) {
        float2 v = s_op[i];
        int cx = max(0, min(15, (int)(v.x * 16.0f)));
        int cy = max(0, min(15, (int)(v.y * 16.0f)));
        int p = atomicAdd(&s_strt[morton4(cx, cy)], 1);
        s_px[p] = v.x; s_py[p] = v.y; s_oi[p] = i;
    }
    __syncthreads();

    // ---- registers: warp owns sorted [wid*512, wid*512+512) ----
    const int wbase = wid * 512;
    unsigned long long nx[8], ny[8];
    int   oidx[16];
    float dist[16];
    float lminx = 1e30f, lmaxx = -1e30f, lminy = 1e30f, lmaxy = -1e30f;
#pragma unroll
    for (int jj = 0; jj < 8; jj++) {
        int p0 = wbase + lane + 64 * jj;
        int p1 = p0 + 32;
        float x0 = s_px[p0], y0 = s_py[p0];
        float x1 = s_px[p1], y1 = s_py[p1];
        oidx[2*jj]   = s_oi[p0];
        oidx[2*jj+1] = s_oi[p1];
        nx[jj] = f2pack(-x0, -x1);
        ny[jj] = f2pack(-y0, -y1);
        dist[2*jj] = INFINITY; dist[2*jj+1] = INFINITY;
        lminx = fminf(lminx, fminf(x0, x1)); lmaxx = fmaxf(lmaxx, fmaxf(x0, x1));
        lminy = fminf(lminy, fminf(y0, y1)); lmaxy = fmaxf(lmaxy, fmaxf(y0, y1));
    }
    const float bminx = __uint_as_float(__reduce_min_sync(0xffffffffu, __float_as_uint(lminx)));
    const float bmaxx = __uint_as_float(__reduce_max_sync(0xffffffffu, __float_as_uint(lmaxx)));
    const float bminy = __uint_as_float(__reduce_min_sync(0xffffffffu, __float_as_uint(lminy)));
    const float bmaxy = __uint_as_float(__reduce_max_sync(0xffffffffu, __float_as_uint(lmaxy)));

    float bx, by;
    { float2 p0 = s_op[0]; bx = p0.x; by = p0.y; }
    if (tid == 0) g_pivot_idx[bb * MM] = 0;

    float m_w = INFINITY;
    unsigned long long cached_key = 0;

    for (int s = 1; s < MM; s++) {
        float ddx = fmaxf(fmaxf(bminx - bx, bx - bmaxx), 0.0f);
        float ddy = fmaxf(fmaxf(bminy - by, by - bmaxy), 0.0f);
        float dlow2 = ddx * ddx + ddy * ddy;

        unsigned long long key;
        if (dlow2 * 0.999f > m_w) {
            key = cached_key;              // provably no dist can change
        } else {
            const unsigned long long bx2 = f2pack(bx, bx);
            const unsigned long long by2 = f2pack(by, by);
            float m = -INFINITY;
#pragma unroll
            for (int j = 0; j < 8; j++) {
                unsigned long long dx = addx2(nx[j], bx2);   // bx - px
                unsigned long long dy = addx2(ny[j], by2);   // by - py
                unsigned long long d  = addx2(mulx2(dx, dx), mulx2(dy, dy));
                float d0, d1; f2unpack(d, &d0, &d1);
                dist[2*j]   = fminf(dist[2*j],   d0);
                dist[2*j+1] = fminf(dist[2*j+1], d1);
                m = fmaxf(m, fmaxf(dist[2*j], dist[2*j+1]));
            }
            unsigned wmax = __reduce_max_sync(0xffffffffu, __float_as_uint(m));
            unsigned cand = 0xffffffffu;
            if (__float_as_uint(m) == wmax) {
                const float mm = __uint_as_float(wmax);
#pragma unroll
                for (int j = 0; j < 16; j++)
                    if (dist[j] == mm) {
                        unsigned gi = (unsigned)oidx[j];
                        cand = (gi < cand) ? gi : cand;
                    }
            }
            unsigned wmin = __reduce_min_sync(0xffffffffu, cand);
            key = ((unsigned long long)wmax << 32) | (unsigned)(~wmin);
            cached_key = key;
            m_w = __uint_as_float(wmax);
        }
        if (lane == 0) s_key[(s & 1) * 16 + wid] = key;
        __syncthreads();
        const ulonglong2* sk2 = (const ulonglong2*)(s_key + (s & 1) * 16);
        unsigned long long t8[8];
#pragma unroll
        for (int w = 0; w < 8; w++) {
            ulonglong2 v2 = sk2[w];
            t8[w] = u64max(v2.x, v2.y);
        }
        unsigned long long best = u64max(u64max(u64max(t8[0], t8[1]), u64max(t8[2], t8[3])),
                                         u64max(u64max(t8[4], t8[5]), u64max(t8[6], t8[7])));
        int bi = (int)(~(unsigned)(best & 0xffffffffu));
        float2 bp = s_op[bi];              // LDS.64, not LDG
        bx = bp.x; by = bp.y;
        if (tid == 0) g_pivot_idx[bb * MM + s] = bi;
    }
}

// ----------------------------------------------------------------------------
// Fused kernel: blocks 0,1 -> FPS; blocks 2..147 -> persistent GEMM
// ----------------------------------------------------------------------------
__global__ void __launch_bounds__(512, 1) gemm_fps_kernel(const float* __restrict__ x,
                                                          const float* __restrict__ pos)
{
    extern __shared__ char smem[];
    if (blockIdx.x < 2) { fps_body(pos, blockIdx.x, smem); return; }

    const uint32_t sb = smem_u32(smem);
    const int tid  = threadIdx.x;
    const int wid  = tid >> 5, lane = tid & 31;
    const int wm   = wid & 3;        // m-slice (32 rows)
    const int wn   = wid >> 2;       // n-slice (32 cols)

    const uint32_t a_off = (uint32_t)(((wm * 32 + (lane & 15)) * TSTRIDE + ((lane >> 4) << 3)) * 2);
    const uint32_t b_off = (uint32_t)(((wn * 32 + ((lane >> 4) << 3) + (lane & 7)) * TSTRIDE
                                      + (((lane >> 3) & 1) << 3)) * 2);

    for (int m = (int)blockIdx.x - 2; m < MTILES; m += GEMM_CTAS) {
        {
            const char* bh = (const char*)g_whi;
            const char* bl = (const char*)g_wlo;
            for (int i = tid; i < 2048; i += 512) {
                int row = i >> 4, ch = i & 15;
                uint32_t off = (uint32_t)((row * TSTRIDE + ch * 8) * 2);
                cp16(sb + SM_B0 + off, bh + i * 16);
                cp16(sb + SM_B0 + TILE_B + off, bl + i * 16);
            }
            CP_COMMIT();
        }

        {
            const float4* xa = (const float4*)(x + (size_t)m * 128 * 128);
            for (int i = tid; i < 4096; i += 512) {
                int row = i >> 5, c = (i & 31) * 4;
                float4 v = xa[i];
                __nv_bfloat16 h0 = __float2bfloat16(v.x);
                __nv_bfloat16 h1 = __float2bfloat16(v.y);
                __nv_bfloat16 h2 = __float2bfloat16(v.z);
                __nv_bfloat16 h3 = __float2bfloat16(v.w);
                __nv_bfloat16 l0 = __float2bfloat16(v.x - __bfloat162float(h0));
                __nv_bfloat16 l1 = __float2bfloat16(v.y - __bfloat162float(h1));
                __nv_bfloat16 l2 = __float2bfloat16(v.z - __bfloat162float(h2));
                __nv_bfloat16 l3 = __float2bfloat16(v.w - __bfloat162float(h3));
                __nv_bfloat162* dh = (__nv_bfloat162*)(smem + SM_AHI + (row * TSTRIDE + c) * 2);
                __nv_bfloat162* dl = (__nv_bfloat162*)(smem + SM_ALO + (row * TSTRIDE + c) * 2);
                __nv_bfloat162 hp0; hp0.x = h0; hp0.y = h1;
                __nv_bfloat162 hp1; hp1.x = h2; hp1.y = h3;
                __nv_bfloat162 lp0; lp0.x = l0; lp0.y = l1;
                __nv_bfloat162 lp1; lp1.x = l2; lp1.y = l3;
                dh[0] = hp0; dh[1] = hp1;
                dl[0] = lp0; dl[1] = lp1;
            }
        }

        for (int nt = 0; nt < NTILES; nt++) {
            const uint32_t bufc = sb + ((nt & 1) ? SM_B1 : SM_B0);

            if (nt + 1 < NTILES) {
                const char* bh = (const char*)(g_whi + (size_t)(nt + 1) * 16384);
                const char* bl = (const char*)(g_wlo + (size_t)(nt + 1) * 16384);
                uint32_t dst = sb + (((nt + 1) & 1) ? SM_B1 : SM_B0);
                for (int i = tid; i < 2048; i += 512) {
                    int row = i >> 4, ch = i & 15;
                    uint32_t off = (uint32_t)((row * TSTRIDE + ch * 8) * 2);
                    cp16(dst + off, bh + i * 16);
                    cp16(dst + TILE_B + off, bl + i * 16);
                }
                CP_COMMIT();
                CP_WAIT(1);
            } else {
                CP_WAIT(0);
            }
            __syncthreads();

            float acc[32];
#pragma unroll
            for (int i = 0; i < 32; i++) acc[i] = 0.f;

#pragma unroll
            for (int pass = 0; pass < 3; pass++) {
                const uint32_t sa  = sb + (pass == 2 ? SM_ALO : SM_AHI) + a_off;
                const uint32_t sbb = bufc + (pass == 1 ? TILE_B : 0) + b_off;
#pragma unroll
                for (int ks = 0; ks < 8; ks++) {
                    uint32_t a0[4], a1[4];
                    ldsm_x4(a0, sa + ks * 32);
                    ldsm_x4(a1, sa + 16 * TSTRIDE * 2 + ks * 32);
#pragma unroll
                    for (int j2 = 0; j2 < 2; j2++) {
                        uint32_t b[4];
                        ldsm_x4(b, sbb + j2 * 16 * TSTRIDE * 2 + ks * 32);
                        mma16816(acc + (0 * 4 + j2 * 2 + 0) * 4, a0, b);
                        mma16816(acc + (0 * 4 + j2 * 2 + 1) * 4, a0, b + 2);
                        mma16816(acc + (1 * 4 + j2 * 2 + 0) * 4, a1, b);
                        mma16816(acc + (1 * 4 + j2 * 2 + 1) * 4, a1, b + 2);
                    }
                }
            }
            __syncthreads();

            {
                const int rbase = m * 128 + wm * 32 + (lane >> 2);
                const int cbase = nt * 128 + wn * 32 + (lane & 3) * 2;
#pragma unroll
                for (int i = 0; i < 2; i++) {
#pragma unroll
                    for (int j = 0; j < 4; j++) {
                        const float* c = acc + (i * 4 + j) * 4;
                        int r0 = rbase + i * 16;
                        int cc = cbase + j * 8;
                        *(float2*)(g_P + (size_t)r0 * QKVC + cc)       = make_float2(c[0], c[1]);
                        *(float2*)(g_P + (size_t)(r0 + 8) * QKVC + cc) = make_float2(c[2], c[3]);
                    }
                }
            }
        }
        __syncthreads();
    }
}

// ----------------------------------------------------------------------------
// Kernel 2: KNN (warp per pivot) + writes pivot_pos to output tail
// ----------------------------------------------------------------------------
__global__ void __launch_bounds__(256) knn_kernel(const float* __restrict__ pos,
                                                  float* __restrict__ outp,
                                                  int write_tail)
{
    const int gw   = blockIdx.x * (blockDim.x >> 5) + (threadIdx.x >> 5);
    const int lane = threadIdx.x & 31;
    const int bb   = gw >> 10;
    const float2* pb = (const float2*)(pos + (size_t)bb * NN * 2);
    const unsigned full = 0xffffffffu;

    const int pidx = g_pivot_idx[gw];
    const float2 pv = pb[pidx];
    const float a = __fadd_rn(__fmul_rn(pv.x, pv.x), __fmul_rn(pv.y, pv.y));

    float d[9]; int id[9];
#pragma unroll
    for (int q = 0; q < 9; q++) { d[q] = INFINITY; id[q] = 0x7fffffff; }

    for (int p = lane; p < NN; p += 32) {
        float2 q2 = pb[p];
        float b2  = __fadd_rn(__fmul_rn(q2.x, q2.x), __fmul_rn(q2.y, q2.y));
        float dot = __fadd_rn(__fmul_rn(pv.x, q2.x), __fmul_rn(pv.y, q2.y));
        float d2  = __fsub_rn(__fadd_rn(a, b2), __fmul_rn(2.0f, dot));
        if (d2 < d[8] || (d2 == d[8] && p < id[8])) {
            d[8] = d2; id[8] = p;
#pragma unroll
            for (int q = 8; q > 0; q--) {
                bool sw = (d[q] < d[q-1]) || (d[q] == d[q-1] && id[q] < id[q-1]);
                if (sw) {
                    float tv = d[q]; d[q] = d[q-1]; d[q-1] = tv;
                    int   ti = id[q]; id[q] = id[q-1]; id[q-1] = ti;
                }
            }
        }
    }
#pragma unroll
    for (int r = 0; r < 9; r++) {
        float bv = d[0]; int bi = id[0]; int bl = lane;
#pragma unroll
        for (int off = 16; off > 0; off >>= 1) {
            float ov = __shfl_down_sync(full, bv, off);
            int   oi = __shfl_down_sync(full, bi, off);
            int   ol = __shfl_down_sync(full, bl, off);
            if (ov < bv || (ov == bv && oi < bi)) { bv = ov; bi = oi; bl = ol; }
        }
        bi = __shfl_sync(full, bi, 0);
        bl = __shfl_sync(full, bl, 0);
        if (lane == bl) {
#pragma unroll
            for (int q = 0; q < 8; q++) { d[q] = d[q+1]; id[q] = id[q+1]; }
            d[8] = INFINITY; id[8] = 0x7fffffff;
        }
        if (lane == 0) {
            g_nbr[gw * KK + r] = bi;
            float2 q2 = pb[bi];
            g_rel[(gw * KK + r) * 2 + 0] = __fsub_rn(q2.x, pv.x);
            g_rel[(gw * KK + r) * 2 + 1] = __fsub_rn(q2.y, pv.y);
        }
    }
    if (lane == 0 && write_tail) {
        outp[OUT_ELEMS + gw * 2 + 0] = pv.x;
        outp[OUT_ELEMS + gw * 2 + 1] = pv.y;
    }
}

// ----------------------------------------------------------------------------
// sin/cos with explicit Cody-Waite range reduction (safe under fast-math)
// ----------------------------------------------------------------------------
__device__ __forceinline__ void sincos_red(float f, float* sn, float* cs)
{
    const float INV2PI = 0.15915494309189535f;
    const float C1 = 6.28318548202514648f;
    const float C2 = -1.74845560e-7f;
    float kq = rintf(f * INV2PI);
    float r = fmaf(-kq, C1, f);
    r = fmaf(-kq, C2, r);
    *sn = sinf(r);
    *cs = cosf(r);
}

// Kernel 2.5: precompute RoPE sin/cos (t-invariant)
__global__ void __launch_bounds__(256) rope_kernel()
{
    int idx = blockIdx.x * 256 + threadIdx.x;
    if (idx >= NROPE) return;
    int i    = idx & 15;
    int half = (idx >> 4) & 1;
    int rest = idx >> 5;
    int s    = rest % 9;
    int g    = rest / 9;
    float rel = g_rel[(g * KK + s) * 2 + half];
    float invf = __powf(10000.0f, -(float)i * (1.0f / 16.0f));
    float f = rel * 2048.0f * invf;
    float sn, cs;
    sincos_red(f, &sn, &cs);
    g_rsin[idx] = sn;
    g_rcos[idx] = cs;
}

// ----------------------------------------------------------------------------
// Kernel 0: convert W1 (=W_qkv rows 0..127) into bf16 hi/lo, layout [ntile][n][k]
// ----------------------------------------------------------------------------
__global__ void __launch_bounds__(256) wprep_kernel(const float* __restrict__ Wq)
{
    int idx = blockIdx.x * 256 + threadIdx.x;
    if (idx >= NTILES * 16384) return;
    int ntile = idx >> 14;
    int e = idx & 16383;
    int n = e >> 7, k = e & 127;
    float w = Wq[(size_t)k * QKVC + ntile * 128 + n];
    __nv_bfloat16 hi = __float2bfloat16(w);
    __nv_bfloat16 lo = __float2bfloat16(w - __bfloat162float(hi));
    g_whi[idx] = hi;
    g_wlo[idx] = lo;
}

// ----------------------------------------------------------------------------
// Kernel 4: group kernel, warp-per-head (R14 form, unchanged).
// ----------------------------------------------------------------------------
__global__ void __launch_bounds__(256) group_kernel(const float* __restrict__ Wq)
{
    extern __shared__ float sm[];
    float* s_qkv  = sm;                        // 9 * QSTRIDE
    float* s_dots = s_qkv + 9 * QSTRIDE;       // 648
    float* s_w    = s_dots + 648;              // 72
    float* s_rel  = s_w + 72;                  // 18
    int*   s_nbr  = (int*)(s_rel + 18);        // 9 (+pad)

    const int g   = blockIdx.x;
    const int bb  = g >> 12;
    const int tt  = (g >> 10) & 3;
    const int mi  = g & 1023;
    const int tid = threadIdx.x;
    const int base = (bb << 10) + mi;          // b*M + m

    if (tid < 9)  s_nbr[tid] = g_nbr[base * KK + tid];
    if (tid < 18) s_rel[tid] = g_rel[base * KK * 2 + tid];
    __syncthreads();

    // gather: qkv[s] = P[nbr[s]] + rel_x * W2a + rel_y * W2b
    const float* Pbt = g_P + (size_t)((bb * TT + tt)) * NN * QKVC;
    const float* W2a = Wq + (size_t)128 * QKVC;
    const float* W2b = Wq + (size_t)129 * QKVC;
    for (int idx = tid; idx < 9 * 384; idx += 256) {
        int sl = idx / 384;
        int c4 = idx - sl * 384;
        float4 p  = *(const float4*)(Pbt + (size_t)s_nbr[sl] * QKVC + c4 * 4);
        float4 wa = *(const float4*)(W2a + c4 * 4);
        float4 wb = *(const float4*)(W2b + c4 * 4);
        float rx = s_rel[sl * 2], ry = s_rel[sl * 2 + 1];
        float4 r;
        r.x = p.x + rx * wa.x + ry * wb.x;
        r.y = p.y + rx * wa.y + ry * wb.y;
        r.z = p.z + rx * wa.z + ry * wb.z;
        r.w = p.w + rx * wa.w + ry * wb.w;
        *(float4*)(s_qkv + sl * QSTRIDE + c4 * 4) = r;
    }
    __syncthreads();   // the ONLY block barrier

    // ---- warp-per-head pipeline: warp h owns head h ----
    const int h = tid >> 5;            // head = warp id
    const int lane = tid & 31;

    // RoPE: lane -> (half, i)
    {
        const int half = lane >> 4, i = lane & 15;
        const int bq = h * 64 + half * 32 + i;
#pragma unroll
        for (int s = 0; s < 9; s++) {
            int ridx = ((base * KK + s) * 2 + half) * 16 + i;
            float sn = g_rsin[ridx];
            float cs = g_rcos[ridx];
            float* row = s_qkv + s * QSTRIDE;
            float qa = row[bq], qb = row[bq + 16];
            row[bq]      = qa * cs - qb * sn;
            row[bq + 16] = qb * cs + qa * sn;
            float ka = row[512 + bq], kb = row[512 + bq + 16];
            row[512 + bq]      = ka * cs - kb * sn;
            row[512 + bq + 16] = kb * cs + ka * sn;
        }
    }
    __syncwarp();

    // dots[i][j] for this head (81 dots striped over lanes)
    for (int idx = lane; idx < 81; idx += 32) {
        int qi = idx / 9, kj = idx - qi * 9;
        const float* qp = s_qkv + qi * QSTRIDE + h * 64;
        const float* kp = s_qkv + kj * QSTRIDE + 512 + h * 64;
        float a2 = 0.f;
#pragma unroll
        for (int dd = 0; dd < 64; dd++) a2 = fmaf(qp[dd], kp[dd], a2);
        s_dots[h * 81 + idx] = a2 * 0.125f;
    }
    __syncwarp();

    // softmax per row (9 rows, lanes 0..8)
    if (lane < 9) {
        float* row = s_dots + h * 81 + lane * 9;
        float mx = row[0];
#pragma unroll
        for (int j = 1; j < 9; j++) mx = fmaxf(mx, row[j]);
        float sum = 0.f;
#pragma unroll
        for (int j = 0; j < 9; j++) { float e = expf(row[j] - mx); row[j] = e; sum += e; }
        float inv = 1.0f / sum;
#pragma unroll
        for (int j = 0; j < 9; j++) row[j] *= inv;
    }
    __syncwarp();

    // column sums: w[j] = sum_i attn[i][j] (lanes 0..8)
    if (lane < 9) {
        float s2 = 0.f;
#pragma unroll
        for (int i = 0; i < 9; i++) s2 += s_dots[h * 81 + i * 9 + lane];
        s_w[h * 9 + lane] = s2;
    }
    __syncwarp();

    // obar: 64 dims for this head, 2 per lane
    for (int dd = lane; dd < 64; dd += 32) {
        float a3 = 0.f;
#pragma unroll
        for (int j = 0; j < 9; j++)
            a3 = fmaf(s_w[h * 9 + j], s_qkv[j * QSTRIDE + 1024 + h * 64 + dd], a3);
        g_obar[(size_t)g * 512 + h * 64 + dd] = a3 * (1.0f / 9.0f);
    }
}

// ----------------------------------------------------------------------------
// Kernel 5: out = obar @ W_out + b_out   (8192 x 128 x 512)
// ----------------------------------------------------------------------------
#define OPROWS 64
__global__ void __launch_bounds__(256) outproj_kernel(const float* __restrict__ Wo,
                                                      const float* __restrict__ bo,
                                                      float* __restrict__ out)
{
    extern __shared__ float smo[];
    float* sA = smo;             // 64 x 128
    float* sB = sA + OPROWS*128; // 128 x 128

    const int row0 = blockIdx.x * OPROWS;
    const int tid = threadIdx.x;
    const int tr = tid >> 4, tc = tid & 15;

    float acc[4][8];
#pragma unroll
    for (int i = 0; i < 4; i++)
#pragma unroll
        for (int j = 0; j < 8; j++) acc[i][j] = 0.f;

    for (int kc = 0; kc < 4; kc++) {
        __syncthreads();
        for (int i = tid; i < OPROWS * 32; i += 256) {
            int r = i >> 5, c4 = (i & 31) * 4;
            *(float4*)(sA + r * 128 + c4) =
                *(const float4*)(g_obar + (size_t)(row0 + r) * 512 + kc * 128 + c4);
        }
        for (int i = tid; i < 128 * 32; i += 256) {
            int r = i >> 5, c4 = (i & 31) * 4;
            *(float4*)(sB + r * 128 + c4) =
                *(const float4*)(Wo + (size_t)(kc * 128 + r) * 128 + c4);
        }
        __syncthreads();
        for (int k = 0; k < 128; k++) {
            float b8[8];
#pragma unroll
            for (int j = 0; j < 8; j++) b8[j] = sB[k * 128 + tc + 16 * j];
#pragma unroll
            for (int i = 0; i < 4; i++) {
                float a = sA[(tr * 4 + i) * 128 + k];
#pragma unroll
                for (int j = 0; j < 8; j++) acc[i][j] = fmaf(a, b8[j], acc[i][j]);
            }
        }
    }
#pragma unroll
    for (int i = 0; i < 4; i++) {
        int row = row0 + tr * 4 + i;
#pragma unroll
        for (int j = 0; j < 8; j++) {
            int c = tc + 16 * j;
            out[(size_t)row * 128 + c] = acc[i][j] + bo[c];
        }
    }
}

// ----------------------------------------------------------------------------
// Launch (dummies keep the ncu capture window on gemm_fps_kernel)
// ----------------------------------------------------------------------------
extern "C" void kernel_launch(void* const* d_in, const int* in_sizes, int n_in,
                              void* d_out, int out_size)
{
    const float* x   = (const float*)d_in[0];
    const float* pos = (const float*)d_in[1];
    const float* Wq  = (const float*)d_in[2];
    const float* Wo  = (const float*)d_in[3];
    const float* bo  = (const float*)d_in[4];
    float* out = (float*)d_out;

    int write_tail = (out_size >= OUT_ELEMS + TAIL) ? 1 : 0;

    const int group_smem = (9 * QSTRIDE + 648 + 72 + 18 + 16) * 4;
    const int op_smem = (OPROWS * 128 + 128 * 128) * 4;

    static int attr_set = 0;
    if (!attr_set) {
        cudaFuncSetAttribute(gemm_fps_kernel, cudaFuncAttributeMaxDynamicSharedMemorySize, GEMM_SMEM);
        cudaFuncSetAttribute(group_kernel, cudaFuncAttributeMaxDynamicSharedMemorySize, group_smem);
        cudaFuncSetAttribute(outproj_kernel, cudaFuncAttributeMaxDynamicSharedMemorySize, op_smem);
        attr_set = 1;
    }

    wprep_kernel<<<(NTILES * 16384 + 255) / 256, 256>>>(Wq);
    dummy_kernel<<<1, 32>>>();
    dummy_kernel<<<1, 32>>>();
    gemm_fps_kernel<<<2 + GEMM_CTAS, 512, GEMM_SMEM>>>(x, pos);
    knn_kernel<<<(BB * MM) / 8, 256>>>(pos, out, write_tail);
    rope_kernel<<<(NROPE + 255) / 256, 256>>>();
    group_kernel<<<BB * TT * MM, 256, group_smem>>>(Wq);
    outproj_kernel<<<BB * TT * MM / OPROWS, 256, op_smem>>>(Wo, bo, out);
}